// round 13
// baseline (speedup 1.0000x reference)
#include <cuda_runtime.h>
#include <cuda_bf16.h>
#include <mma.h>
#include <math.h>
#include <stdint.h>

using namespace nvcuda;

#define U_NUM 100000
#define I_NUM 50000
#define N_NUM 150000
#define E_NUM 1200000
#define D 64
#define F_DIM 384
#define EPS 1e-8f
#define ELL_W 64

// Scratch (allocation-free rule: __device__ globals; zero-initialized at load)
__device__ float g_ego[(size_t)N_NUM * D];
__device__ float g_buf0[(size_t)N_NUM * D];
__device__ float g_buf1[(size_t)N_NUM * D];
__device__ float g_buf2[(size_t)N_NUM * D];
__device__ int   g_cnt[N_NUM];
__device__ int2  g_elle[(size_t)N_NUM * ELL_W];   // packed (col, val-bits); tail slots stay 0

__device__ __forceinline__ float tanh_fast(float x) {
    float r;
    asm("tanh.approx.f32 %0, %1;" : "=f"(r) : "f"(x));
    return r;
}

// ---- L2 cache-hint policies (createpolicy + cache_hint form)
__device__ __forceinline__ uint64_t mk_policy_last() {
    uint64_t p;
    asm("createpolicy.fractional.L2::evict_last.b64 %0, 1.0;" : "=l"(p));
    return p;
}
__device__ __forceinline__ uint64_t mk_policy_first() {
    uint64_t p;
    asm("createpolicy.fractional.L2::evict_first.b64 %0, 1.0;" : "=l"(p));
    return p;
}
__device__ __forceinline__ float4 ldg_f4_pol(const float4* p, uint64_t pol) {
    float4 v;
    asm("ld.global.nc.L2::cache_hint.v4.f32 {%0,%1,%2,%3}, [%4], %5;"
        : "=f"(v.x), "=f"(v.y), "=f"(v.z), "=f"(v.w) : "l"(p), "l"(pol));
    return v;
}
__device__ __forceinline__ int4 ldg_i4_pol(const int4* p, uint64_t pol) {
    int4 v;
    asm("ld.global.nc.L2::cache_hint.v4.b32 {%0,%1,%2,%3}, [%4], %5;"
        : "=r"(v.x), "=r"(v.y), "=r"(v.z), "=r"(v.w) : "l"(p), "l"(pol));
    return v;
}
__device__ __forceinline__ void stg_f4_pol(float4* p, float4 v, uint64_t pol) {
    asm volatile("st.global.L2::cache_hint.v4.f32 [%0], {%1,%2,%3,%4}, %5;"
                 :: "l"(p), "f"(v.x), "f"(v.y), "f"(v.z), "f"(v.w), "l"(pol) : "memory");
}

// ---------------- fused preamble: [gemm tiles | ELL build | user init], one kernel
#define BM 128
#define GK 32
#define LDA 40
#define LDW 40

#define GEMM_BLOCKS ((I_NUM + BM - 1) / BM)   // 391
#define BUILD_BLOCKS 320
#define USER_BLOCKS  320
#define PRE_BLOCKS (GEMM_BLOCKS + BUILD_BLOCKS + USER_BLOCKS)

#define SM_AS_HI 0
#define SM_AS_LO (SM_AS_HI + BM * LDA * 2)            // 10240
#define SM_WS_HI (SM_AS_LO + BM * LDA * 2)            // 20480
#define SM_WS_LO (SM_WS_HI + D * LDW * 2)             // 25600
#define SM_MAIN  (SM_WS_LO + D * LDW * 2)             // 30720
#define SM_OS_SZ (8 * 16 * D * 4)                     // 32768
#define SM_TOTAL (SM_OS_SZ > SM_MAIN ? SM_OS_SZ : SM_MAIN)

__device__ __forceinline__ void split_store(__nv_bfloat16* hi, __nv_bfloat16* lo, float v) {
    __nv_bfloat16 h = __float2bfloat16(v);
    *hi = h;
    *lo = __float2bfloat16(v - __bfloat162float(h));
}

__global__ __launch_bounds__(256) void k_preamble(
    const float* __restrict__ A,
    const float* __restrict__ W,
    const float* __restrict__ bias,
    const float* __restrict__ gi,
    const int* __restrict__ rows, const int* __restrict__ cols,
    const float* __restrict__ vals,
    const float* __restrict__ user_fea,
    const float* __restrict__ gu,
    int* __restrict__ cnt, int2* __restrict__ elle,
    float* __restrict__ ego) {
    __shared__ __align__(16) char smem[SM_TOTAL];
    int blk = blockIdx.x;
    int t = threadIdx.x;

    if (blk < GEMM_BLOCKS) {
        __nv_bfloat16 (*AsH)[LDA] = (__nv_bfloat16(*)[LDA])(smem + SM_AS_HI);
        __nv_bfloat16 (*AsL)[LDA] = (__nv_bfloat16(*)[LDA])(smem + SM_AS_LO);
        __nv_bfloat16 (*WsH)[LDW] = (__nv_bfloat16(*)[LDW])(smem + SM_WS_HI);
        __nv_bfloat16 (*WsL)[LDW] = (__nv_bfloat16(*)[LDW])(smem + SM_WS_LO);

        int w = t >> 5;
        int lane = t & 31;
        int r0 = blk * BM;

        wmma::fragment<wmma::accumulator, 16, 16, 16, float> cfrag[4];
        #pragma unroll
        for (int nf = 0; nf < 4; nf++) wmma::fill_fragment(cfrag[nf], 0.0f);

        int ar = t >> 1,  ac = (t & 1) * 16;
        int wr = t >> 2,  wc = (t & 3) * 8;

        for (int k0 = 0; k0 < F_DIM; k0 += GK) {
            {
                int gr = r0 + ar;
                if (gr < I_NUM) {
                    const float4* src = (const float4*)(A + (size_t)gr * F_DIM + k0 + ac);
                    #pragma unroll
                    for (int s = 0; s < 4; s++) {
                        float4 v = __ldg(src + s);
                        split_store(&AsH[ar][ac + s * 4],     &AsL[ar][ac + s * 4],     v.x);
                        split_store(&AsH[ar][ac + s * 4 + 1], &AsL[ar][ac + s * 4 + 1], v.y);
                        split_store(&AsH[ar][ac + s * 4 + 2], &AsL[ar][ac + s * 4 + 2], v.z);
                        split_store(&AsH[ar][ac + s * 4 + 3], &AsL[ar][ac + s * 4 + 3], v.w);
                    }
                } else {
                    #pragma unroll
                    for (int s = 0; s < 16; s++) {
                        AsH[ar][ac + s] = __float2bfloat16(0.f);
                        AsL[ar][ac + s] = __float2bfloat16(0.f);
                    }
                }
            }
            {
                const float4* src = (const float4*)(W + (size_t)wr * F_DIM + k0 + wc);
                #pragma unroll
                for (int s = 0; s < 2; s++) {
                    float4 v = __ldg(src + s);
                    split_store(&WsH[wr][wc + s * 4],     &WsL[wr][wc + s * 4],     v.x);
                    split_store(&WsH[wr][wc + s * 4 + 1], &WsL[wr][wc + s * 4 + 1], v.y);
                    split_store(&WsH[wr][wc + s * 4 + 2], &WsL[wr][wc + s * 4 + 2], v.z);
                    split_store(&WsH[wr][wc + s * 4 + 3], &WsL[wr][wc + s * 4 + 3], v.w);
                }
            }
            __syncthreads();

            #pragma unroll
            for (int kk = 0; kk < GK; kk += 16) {
                wmma::fragment<wmma::matrix_a, 16, 16, 16, __nv_bfloat16, wmma::row_major> aH, aL;
                wmma::load_matrix_sync(aH, &AsH[w * 16][kk], LDA);
                wmma::load_matrix_sync(aL, &AsL[w * 16][kk], LDA);
                #pragma unroll
                for (int nf = 0; nf < 4; nf++) {
                    wmma::fragment<wmma::matrix_b, 16, 16, 16, __nv_bfloat16, wmma::col_major> bH, bL;
                    wmma::load_matrix_sync(bH, &WsH[nf * 16][kk], LDW);
                    wmma::load_matrix_sync(bL, &WsL[nf * 16][kk], LDW);
                    wmma::mma_sync(cfrag[nf], aH, bH, cfrag[nf]);
                    wmma::mma_sync(cfrag[nf], aH, bL, cfrag[nf]);
                    wmma::mma_sync(cfrag[nf], aL, bH, cfrag[nf]);
                }
            }
            __syncthreads();
        }

        float (*Os)[16][D] = (float(*)[16][D])smem;
        #pragma unroll
        for (int nf = 0; nf < 4; nf++)
            wmma::store_matrix_sync(&Os[w][0][nf * 16], cfrag[nf], D, wmma::mem_row_major);
        __syncwarp();

        for (int idx = lane; idx < 16 * D; idx += 32) {
            int i = idx >> 6;
            int n = idx & 63;
            int r = r0 + w * 16 + i;
            if (r < I_NUM) {
                float c = Os[w][i][n];
                float sn = gi[n] + gi[D + n] + gi[2 * D + n];
                ego[(size_t)(U_NUM + r) * D + n] = tanh_fast(c + bias[n]) + sn;
            }
        }
    } else if (blk < GEMM_BLOCKS + BUILD_BLOCKS) {
        int base = (blk - GEMM_BLOCKS) * 256 + t;
        for (int e = base; e < E_NUM; e += BUILD_BLOCKS * 256) {
            int r = __ldg(rows + e);
            int slot = atomicAdd(cnt + r, 1);
            if (slot < ELL_W) {
                int2 p;
                p.x = __ldg(cols + e);
                p.y = __float_as_int(__ldg(vals + e));
                elle[(size_t)r * ELL_W + slot] = p;
            }
        }
    } else {
        int wbase = (blk - GEMM_BLOCKS - BUILD_BLOCKS) * 8 + (t >> 5);
        int lane = t & 31;
        int d0 = lane * 2;
        float s0 = gu[d0]     + gu[D + d0]     + gu[2 * D + d0];
        float s1 = gu[d0 + 1] + gu[D + d0 + 1] + gu[2 * D + d0 + 1];
        for (int u = wbase; u < U_NUM; u += USER_BLOCKS * 8) {
            float2 v = ((const float2*)(user_fea + (size_t)u * D))[lane];
            v.x += s0; v.y += s1;
            ((float2*)(ego + (size_t)u * D))[lane] = v;
        }
    }
}

// ---------------- layer core: y_row = w * (A x)_row  (half-warp per row)
// Latency-chain break: batch 0 (8 edges) processed UNCONDITIONALLY (tail slots
// are zero -> contribute nothing), so edge loads don't wait on cnt; cnt only
// gates the rare c>8 continuation. ego (and FINAL's y0..y2) loads hoisted
// before the gather loop to overlap it.
template <bool FINAL>
__global__ __launch_bounds__(256) void k_layer_t(
    const float* __restrict__ x, float* __restrict__ y,
    const int* __restrict__ cnt, const int2* __restrict__ elle,
    const float* __restrict__ ego,
    const float* __restrict__ y0, const float* __restrict__ y1,
    const float* __restrict__ y2) {
    int warp = (blockIdx.x * blockDim.x + threadIdx.x) >> 5;
    int lane = threadIdx.x & 31;
    int half = lane >> 4;
    int hl   = lane & 15;
    int row  = warp * 2 + half;
    if (row >= N_NUM) return;

    uint64_t pL = mk_policy_last();
    uint64_t pF = mk_policy_first();

    size_t base = (size_t)row * D;
    const int4* ep4 = (const int4*)(elle + (size_t)row * ELL_W);

    // all independent loads issue up front: cnt, batch-0 edges, ego (+ finals)
    int c = min(__ldg(cnt + row), ELL_W);
    int4 q0 = ldg_i4_pol(ep4,     pF);
    int4 q1 = ldg_i4_pol(ep4 + 1, pF);
    int4 q2 = ldg_i4_pol(ep4 + 2, pF);
    int4 q3 = ldg_i4_pol(ep4 + 3, pF);
    float4 ev = ldg_f4_pol((const float4*)(ego + base) + hl, pF);
    float4 fa, fb, fc;
    if (FINAL) {
        fa = ldg_f4_pol((const float4*)(y0 + base) + hl, pF);
        fb = ldg_f4_pol((const float4*)(y1 + base) + hl, pF);
        fc = ldg_f4_pol((const float4*)(y2 + base) + hl, pF);
    }

    float4 acc = make_float4(0.f, 0.f, 0.f, 0.f);

    // batch 0: unconditional
    {
        float4 x0 = ldg_f4_pol((const float4*)(x + (size_t)q0.x * D) + hl, pL);
        float4 x1 = ldg_f4_pol((const float4*)(x + (size_t)q0.z * D) + hl, pL);
        float4 x2 = ldg_f4_pol((const float4*)(x + (size_t)q1.x * D) + hl, pL);
        float4 x3 = ldg_f4_pol((const float4*)(x + (size_t)q1.z * D) + hl, pL);
        float4 x4 = ldg_f4_pol((const float4*)(x + (size_t)q2.x * D) + hl, pL);
        float4 x5 = ldg_f4_pol((const float4*)(x + (size_t)q2.z * D) + hl, pL);
        float4 x6 = ldg_f4_pol((const float4*)(x + (size_t)q3.x * D) + hl, pL);
        float4 x7 = ldg_f4_pol((const float4*)(x + (size_t)q3.z * D) + hl, pL);
        float v0 = __int_as_float(q0.y), v1 = __int_as_float(q0.w);
        float v2 = __int_as_float(q1.y), v3 = __int_as_float(q1.w);
        float v4 = __int_as_float(q2.y), v5 = __int_as_float(q2.w);
        float v6 = __int_as_float(q3.y), v7 = __int_as_float(q3.w);
        acc.x = fmaf(v0, x0.x, acc.x); acc.y = fmaf(v0, x0.y, acc.y);
        acc.z = fmaf(v0, x0.z, acc.z); acc.w = fmaf(v0, x0.w, acc.w);
        acc.x = fmaf(v1, x1.x, acc.x); acc.y = fmaf(v1, x1.y, acc.y);
        acc.z = fmaf(v1, x1.z, acc.z); acc.w = fmaf(v1, x1.w, acc.w);
        acc.x = fmaf(v2, x2.x, acc.x); acc.y = fmaf(v2, x2.y, acc.y);
        acc.z = fmaf(v2, x2.z, acc.z); acc.w = fmaf(v2, x2.w, acc.w);
        acc.x = fmaf(v3, x3.x, acc.x); acc.y = fmaf(v3, x3.y, acc.y);
        acc.z = fmaf(v3, x3.z, acc.z); acc.w = fmaf(v3, x3.w, acc.w);
        acc.x = fmaf(v4, x4.x, acc.x); acc.y = fmaf(v4, x4.y, acc.y);
        acc.z = fmaf(v4, x4.z, acc.z); acc.w = fmaf(v4, x4.w, acc.w);
        acc.x = fmaf(v5, x5.x, acc.x); acc.y = fmaf(v5, x5.y, acc.y);
        acc.z = fmaf(v5, x5.z, acc.z); acc.w = fmaf(v5, x5.w, acc.w);
        acc.x = fmaf(v6, x6.x, acc.x); acc.y = fmaf(v6, x6.y, acc.y);
        acc.z = fmaf(v6, x6.z, acc.z); acc.w = fmaf(v6, x6.w, acc.w);
        acc.x = fmaf(v7, x7.x, acc.x); acc.y = fmaf(v7, x7.y, acc.y);
        acc.z = fmaf(v7, x7.z, acc.z); acc.w = fmaf(v7, x7.w, acc.w);
    }

    // rare continuation (c > 8)
    for (int b = 8; b < c; b += 8) {
        int q = b >> 1;
        int4 r0 = ldg_i4_pol(ep4 + q,     pF);
        int4 r1 = ldg_i4_pol(ep4 + q + 1, pF);
        int4 r2 = ldg_i4_pol(ep4 + q + 2, pF);
        int4 r3 = ldg_i4_pol(ep4 + q + 3, pF);
        float4 x0 = ldg_f4_pol((const float4*)(x + (size_t)r0.x * D) + hl, pL);
        float4 x1 = ldg_f4_pol((const float4*)(x + (size_t)r0.z * D) + hl, pL);
        float4 x2 = ldg_f4_pol((const float4*)(x + (size_t)r1.x * D) + hl, pL);
        float4 x3 = ldg_f4_pol((const float4*)(x + (size_t)r1.z * D) + hl, pL);
        float4 x4 = ldg_f4_pol((const float4*)(x + (size_t)r2.x * D) + hl, pL);
        float4 x5 = ldg_f4_pol((const float4*)(x + (size_t)r2.z * D) + hl, pL);
        float4 x6 = ldg_f4_pol((const float4*)(x + (size_t)r3.x * D) + hl, pL);
        float4 x7 = ldg_f4_pol((const float4*)(x + (size_t)r3.z * D) + hl, pL);
        float v0 = __int_as_float(r0.y), v1 = __int_as_float(r0.w);
        float v2 = __int_as_float(r1.y), v3 = __int_as_float(r1.w);
        float v4 = __int_as_float(r2.y), v5 = __int_as_float(r2.w);
        float v6 = __int_as_float(r3.y), v7 = __int_as_float(r3.w);
        acc.x = fmaf(v0, x0.x, acc.x); acc.y = fmaf(v0, x0.y, acc.y);
        acc.z = fmaf(v0, x0.z, acc.z); acc.w = fmaf(v0, x0.w, acc.w);
        acc.x = fmaf(v1, x1.x, acc.x); acc.y = fmaf(v1, x1.y, acc.y);
        acc.z = fmaf(v1, x1.z, acc.z); acc.w = fmaf(v1, x1.w, acc.w);
        acc.x = fmaf(v2, x2.x, acc.x); acc.y = fmaf(v2, x2.y, acc.y);
        acc.z = fmaf(v2, x2.z, acc.z); acc.w = fmaf(v2, x2.w, acc.w);
        acc.x = fmaf(v3, x3.x, acc.x); acc.y = fmaf(v3, x3.y, acc.y);
        acc.z = fmaf(v3, x3.z, acc.z); acc.w = fmaf(v3, x3.w, acc.w);
        acc.x = fmaf(v4, x4.x, acc.x); acc.y = fmaf(v4, x4.y, acc.y);
        acc.z = fmaf(v4, x4.z, acc.z); acc.w = fmaf(v4, x4.w, acc.w);
        acc.x = fmaf(v5, x5.x, acc.x); acc.y = fmaf(v5, x5.y, acc.y);
        acc.z = fmaf(v5, x5.z, acc.z); acc.w = fmaf(v5, x5.w, acc.w);
        acc.x = fmaf(v6, x6.x, acc.x); acc.y = fmaf(v6, x6.y, acc.y);
        acc.z = fmaf(v6, x6.z, acc.z); acc.w = fmaf(v6, x6.w, acc.w);
        acc.x = fmaf(v7, x7.x, acc.x); acc.y = fmaf(v7, x7.y, acc.y);
        acc.z = fmaf(v7, x7.z, acc.z); acc.w = fmaf(v7, x7.w, acc.w);
    }

    float dot = acc.x * ev.x + acc.y * ev.y + acc.z * ev.z + acc.w * ev.w;
    float ssy = acc.x * acc.x + acc.y * acc.y + acc.z * acc.z + acc.w * acc.w;
    float sse = ev.x * ev.x + ev.y * ev.y + ev.z * ev.z + ev.w * ev.w;
    #pragma unroll
    for (int o = 8; o; o >>= 1) {
        dot += __shfl_xor_sync(0xffffffffu, dot, o);
        ssy += __shfl_xor_sync(0xffffffffu, ssy, o);
        sse += __shfl_xor_sync(0xffffffffu, sse, o);
    }
    float w = dot / (fmaxf(sqrtf(ssy), EPS) * fmaxf(sqrtf(sse), EPS));
    acc.x *= w; acc.y *= w; acc.z *= w; acc.w *= w;

    if (FINAL) {
        acc.x += ev.x + fa.x + fb.x + fc.x;
        acc.y += ev.y + fa.y + fb.y + fc.y;
        acc.z += ev.z + fa.z + fb.z + fc.z;
        acc.w += ev.w + fa.w + fb.w + fc.w;
        ((float4*)(y + base))[hl] = acc;   // final output: default policy
    } else {
        stg_f4_pol((float4*)(y + base) + hl, acc, pL);
    }
}

extern "C" void kernel_launch(void* const* d_in, const int* in_sizes, int n_in,
                              void* d_out, int out_size) {
    const int*   adj_row  = (const int*)d_in[0];
    const int*   adj_col  = (const int*)d_in[1];
    const float* adj_val  = (const float*)d_in[2];
    const float* user_fea = (const float*)d_in[3];
    const float* item_fea = (const float*)d_in[4];
    const float* g_emb_u  = (const float*)d_in[5];
    const float* g_emb_i  = (const float*)d_in[6];
    const float* mlp_w    = (const float*)d_in[7];
    const float* mlp_b    = (const float*)d_in[8];
    float* acc = (float*)d_out;

    float *ego_p, *b0, *b1, *b2;
    int *cnt_p; int2 *elle_p;
    cudaGetSymbolAddress((void**)&ego_p,  g_ego);
    cudaGetSymbolAddress((void**)&b0,     g_buf0);
    cudaGetSymbolAddress((void**)&b1,     g_buf1);
    cudaGetSymbolAddress((void**)&b2,     g_buf2);
    cudaGetSymbolAddress((void**)&cnt_p,  g_cnt);
    cudaGetSymbolAddress((void**)&elle_p, g_elle);

    cudaMemsetAsync(cnt_p, 0, N_NUM * sizeof(int));
    k_preamble<<<PRE_BLOCKS, 256>>>(item_fea, mlp_w, mlp_b, g_emb_i,
                                    adj_row, adj_col, adj_val,
                                    user_fea, g_emb_u,
                                    cnt_p, elle_p, ego_p);

    int lgrid = (N_NUM / 2 + 7) / 8;
    k_layer_t<false><<<lgrid, 256>>>(ego_p, b0, cnt_p, elle_p, ego_p, b0, b1, b2);
    k_layer_t<false><<<lgrid, 256>>>(b0,    b1, cnt_p, elle_p, ego_p, b0, b1, b2);
    k_layer_t<false><<<lgrid, 256>>>(b1,    b2, cnt_p, elle_p, ego_p, b0, b1, b2);
    k_layer_t<true><<<lgrid, 256>>>(b2,    acc, cnt_p, elle_p, ego_p, b0, b1, b2);
}

// round 14
// speedup vs baseline: 1.1315x; 1.1315x over previous
#include <cuda_runtime.h>
#include <cuda_bf16.h>
#include <mma.h>
#include <math.h>
#include <stdint.h>

using namespace nvcuda;

#define U_NUM 100000
#define I_NUM 50000
#define N_NUM 150000
#define E_NUM 1200000
#define D 64
#define F_DIM 384
#define EPS 1e-8f
#define ELL_W 64

// Scratch (allocation-free rule: __device__ globals; zero-initialized at load)
// cnt invariant: zero at entry to every kernel_launch call (zero-init at load;
// FINAL layer re-zeroes after its read on every call).
__device__ float g_ego[(size_t)N_NUM * D];
__device__ float g_buf0[(size_t)N_NUM * D];
__device__ float g_buf1[(size_t)N_NUM * D];
__device__ float g_buf2[(size_t)N_NUM * D];
__device__ int   g_cnt[N_NUM];
__device__ int2  g_elle[(size_t)N_NUM * ELL_W];   // packed (col, val-bits); tail slots stay 0

__device__ __forceinline__ float tanh_fast(float x) {
    float r;
    asm("tanh.approx.f32 %0, %1;" : "=f"(r) : "f"(x));
    return r;
}

// ---- L2 cache-hint policies (createpolicy + cache_hint form)
__device__ __forceinline__ uint64_t mk_policy_last() {
    uint64_t p;
    asm("createpolicy.fractional.L2::evict_last.b64 %0, 1.0;" : "=l"(p));
    return p;
}
__device__ __forceinline__ uint64_t mk_policy_first() {
    uint64_t p;
    asm("createpolicy.fractional.L2::evict_first.b64 %0, 1.0;" : "=l"(p));
    return p;
}
__device__ __forceinline__ float4 ldg_f4_pol(const float4* p, uint64_t pol) {
    float4 v;
    asm("ld.global.nc.L2::cache_hint.v4.f32 {%0,%1,%2,%3}, [%4], %5;"
        : "=f"(v.x), "=f"(v.y), "=f"(v.z), "=f"(v.w) : "l"(p), "l"(pol));
    return v;
}
__device__ __forceinline__ int4 ldg_i4_pol(const int4* p, uint64_t pol) {
    int4 v;
    asm("ld.global.nc.L2::cache_hint.v4.b32 {%0,%1,%2,%3}, [%4], %5;"
        : "=r"(v.x), "=r"(v.y), "=r"(v.z), "=r"(v.w) : "l"(p), "l"(pol));
    return v;
}
__device__ __forceinline__ void stg_f4_pol(float4* p, float4 v, uint64_t pol) {
    asm volatile("st.global.L2::cache_hint.v4.f32 [%0], {%1,%2,%3,%4}, %5;"
                 :: "l"(p), "f"(v.x), "f"(v.y), "f"(v.z), "f"(v.w), "l"(pol) : "memory");
}

// ---------------- fused preamble: [gemm tiles | ELL build | user init], one kernel
#define BM 128
#define GK 32
#define LDA 40
#define LDW 40

#define GEMM_BLOCKS ((I_NUM + BM - 1) / BM)   // 391
#define BUILD_BLOCKS 320
#define USER_BLOCKS  320
#define PRE_BLOCKS (GEMM_BLOCKS + BUILD_BLOCKS + USER_BLOCKS)

#define SM_AS_HI 0
#define SM_AS_LO (SM_AS_HI + BM * LDA * 2)            // 10240
#define SM_WS_HI (SM_AS_LO + BM * LDA * 2)            // 20480
#define SM_WS_LO (SM_WS_HI + D * LDW * 2)             // 25600
#define SM_MAIN  (SM_WS_LO + D * LDW * 2)             // 30720
#define SM_OS_SZ (8 * 16 * D * 4)                     // 32768
#define SM_TOTAL (SM_OS_SZ > SM_MAIN ? SM_OS_SZ : SM_MAIN)

__device__ __forceinline__ void split_store(__nv_bfloat16* hi, __nv_bfloat16* lo, float v) {
    __nv_bfloat16 h = __float2bfloat16(v);
    *hi = h;
    *lo = __float2bfloat16(v - __bfloat162float(h));
}

__global__ __launch_bounds__(256) void k_preamble(
    const float* __restrict__ A,
    const float* __restrict__ W,
    const float* __restrict__ bias,
    const float* __restrict__ gi,
    const int* __restrict__ rows, const int* __restrict__ cols,
    const float* __restrict__ vals,
    const float* __restrict__ user_fea,
    const float* __restrict__ gu,
    int* __restrict__ cnt, int2* __restrict__ elle,
    float* __restrict__ ego) {
    __shared__ __align__(16) char smem[SM_TOTAL];
    int blk = blockIdx.x;
    int t = threadIdx.x;

    if (blk < GEMM_BLOCKS) {
        __nv_bfloat16 (*AsH)[LDA] = (__nv_bfloat16(*)[LDA])(smem + SM_AS_HI);
        __nv_bfloat16 (*AsL)[LDA] = (__nv_bfloat16(*)[LDA])(smem + SM_AS_LO);
        __nv_bfloat16 (*WsH)[LDW] = (__nv_bfloat16(*)[LDW])(smem + SM_WS_HI);
        __nv_bfloat16 (*WsL)[LDW] = (__nv_bfloat16(*)[LDW])(smem + SM_WS_LO);

        int w = t >> 5;
        int lane = t & 31;
        int r0 = blk * BM;

        wmma::fragment<wmma::accumulator, 16, 16, 16, float> cfrag[4];
        #pragma unroll
        for (int nf = 0; nf < 4; nf++) wmma::fill_fragment(cfrag[nf], 0.0f);

        int ar = t >> 1,  ac = (t & 1) * 16;
        int wr = t >> 2,  wc = (t & 3) * 8;

        for (int k0 = 0; k0 < F_DIM; k0 += GK) {
            {
                int gr = r0 + ar;
                if (gr < I_NUM) {
                    const float4* src = (const float4*)(A + (size_t)gr * F_DIM + k0 + ac);
                    #pragma unroll
                    for (int s = 0; s < 4; s++) {
                        float4 v = __ldg(src + s);
                        split_store(&AsH[ar][ac + s * 4],     &AsL[ar][ac + s * 4],     v.x);
                        split_store(&AsH[ar][ac + s * 4 + 1], &AsL[ar][ac + s * 4 + 1], v.y);
                        split_store(&AsH[ar][ac + s * 4 + 2], &AsL[ar][ac + s * 4 + 2], v.z);
                        split_store(&AsH[ar][ac + s * 4 + 3], &AsL[ar][ac + s * 4 + 3], v.w);
                    }
                } else {
                    #pragma unroll
                    for (int s = 0; s < 16; s++) {
                        AsH[ar][ac + s] = __float2bfloat16(0.f);
                        AsL[ar][ac + s] = __float2bfloat16(0.f);
                    }
                }
            }
            {
                const float4* src = (const float4*)(W + (size_t)wr * F_DIM + k0 + wc);
                #pragma unroll
                for (int s = 0; s < 2; s++) {
                    float4 v = __ldg(src + s);
                    split_store(&WsH[wr][wc + s * 4],     &WsL[wr][wc + s * 4],     v.x);
                    split_store(&WsH[wr][wc + s * 4 + 1], &WsL[wr][wc + s * 4 + 1], v.y);
                    split_store(&WsH[wr][wc + s * 4 + 2], &WsL[wr][wc + s * 4 + 2], v.z);
                    split_store(&WsH[wr][wc + s * 4 + 3], &WsL[wr][wc + s * 4 + 3], v.w);
                }
            }
            __syncthreads();

            #pragma unroll
            for (int kk = 0; kk < GK; kk += 16) {
                wmma::fragment<wmma::matrix_a, 16, 16, 16, __nv_bfloat16, wmma::row_major> aH, aL;
                wmma::load_matrix_sync(aH, &AsH[w * 16][kk], LDA);
                wmma::load_matrix_sync(aL, &AsL[w * 16][kk], LDA);
                #pragma unroll
                for (int nf = 0; nf < 4; nf++) {
                    wmma::fragment<wmma::matrix_b, 16, 16, 16, __nv_bfloat16, wmma::col_major> bH, bL;
                    wmma::load_matrix_sync(bH, &WsH[nf * 16][kk], LDW);
                    wmma::load_matrix_sync(bL, &WsL[nf * 16][kk], LDW);
                    wmma::mma_sync(cfrag[nf], aH, bH, cfrag[nf]);
                    wmma::mma_sync(cfrag[nf], aH, bL, cfrag[nf]);
                    wmma::mma_sync(cfrag[nf], aL, bH, cfrag[nf]);
                }
            }
            __syncthreads();
        }

        float (*Os)[16][D] = (float(*)[16][D])smem;
        #pragma unroll
        for (int nf = 0; nf < 4; nf++)
            wmma::store_matrix_sync(&Os[w][0][nf * 16], cfrag[nf], D, wmma::mem_row_major);
        __syncwarp();

        for (int idx = lane; idx < 16 * D; idx += 32) {
            int i = idx >> 6;
            int n = idx & 63;
            int r = r0 + w * 16 + i;
            if (r < I_NUM) {
                float c = Os[w][i][n];
                float sn = gi[n] + gi[D + n] + gi[2 * D + n];
                ego[(size_t)(U_NUM + r) * D + n] = tanh_fast(c + bias[n]) + sn;
            }
        }
    } else if (blk < GEMM_BLOCKS + BUILD_BLOCKS) {
        int base = (blk - GEMM_BLOCKS) * 256 + t;
        for (int e = base; e < E_NUM; e += BUILD_BLOCKS * 256) {
            int r = __ldg(rows + e);
            int slot = atomicAdd(cnt + r, 1);
            if (slot < ELL_W) {
                int2 p;
                p.x = __ldg(cols + e);
                p.y = __float_as_int(__ldg(vals + e));
                elle[(size_t)r * ELL_W + slot] = p;
            }
        }
    } else {
        int wbase = (blk - GEMM_BLOCKS - BUILD_BLOCKS) * 8 + (t >> 5);
        int lane = t & 31;
        int d0 = lane * 2;
        float s0 = gu[d0]     + gu[D + d0]     + gu[2 * D + d0];
        float s1 = gu[d0 + 1] + gu[D + d0 + 1] + gu[2 * D + d0 + 1];
        for (int u = wbase; u < U_NUM; u += USER_BLOCKS * 8) {
            float2 v = ((const float2*)(user_fea + (size_t)u * D))[lane];
            v.x += s0; v.y += s1;
            ((float2*)(ego + (size_t)u * D))[lane] = v;
        }
    }
}

// ---------------- layer core: y_row = w * (A x)_row  (half-warp per row)
// R12 body with do/while: batch 0 executes before the c-comparison (edge loads
// not gated by cnt), register allocation unchanged. FINAL zeroes cnt[row]
// after use so the next call starts from the zero invariant (no memset).
template <bool FINAL>
__global__ __launch_bounds__(256, 8) void k_layer_t(
    const float* __restrict__ x, float* __restrict__ y,
    int* __restrict__ cnt, const int2* __restrict__ elle,
    const float* __restrict__ ego,
    const float* __restrict__ y0, const float* __restrict__ y1,
    const float* __restrict__ y2) {
    int warp = (blockIdx.x * blockDim.x + threadIdx.x) >> 5;
    int lane = threadIdx.x & 31;
    int half = lane >> 4;
    int hl   = lane & 15;
    int row  = warp * 2 + half;
    if (row >= N_NUM) return;

    uint64_t pL = mk_policy_last();
    uint64_t pF = mk_policy_first();

    int c = min(__ldg((const int*)cnt + row), ELL_W);
    const int4* ep4 = (const int4*)(elle + (size_t)row * ELL_W);
    float4 acc = make_float4(0.f, 0.f, 0.f, 0.f);

    int b = 0;
    do {
        int q = b >> 1;
        int4 q0 = ldg_i4_pol(ep4 + q,     pF);
        int4 q1 = ldg_i4_pol(ep4 + q + 1, pF);
        int4 q2 = ldg_i4_pol(ep4 + q + 2, pF);
        int4 q3 = ldg_i4_pol(ep4 + q + 3, pF);
        float4 x0 = ldg_f4_pol((const float4*)(x + (size_t)q0.x * D) + hl, pL);
        float4 x1 = ldg_f4_pol((const float4*)(x + (size_t)q0.z * D) + hl, pL);
        float4 x2 = ldg_f4_pol((const float4*)(x + (size_t)q1.x * D) + hl, pL);
        float4 x3 = ldg_f4_pol((const float4*)(x + (size_t)q1.z * D) + hl, pL);
        float4 x4 = ldg_f4_pol((const float4*)(x + (size_t)q2.x * D) + hl, pL);
        float4 x5 = ldg_f4_pol((const float4*)(x + (size_t)q2.z * D) + hl, pL);
        float4 x6 = ldg_f4_pol((const float4*)(x + (size_t)q3.x * D) + hl, pL);
        float4 x7 = ldg_f4_pol((const float4*)(x + (size_t)q3.z * D) + hl, pL);
        float v0 = __int_as_float(q0.y), v1 = __int_as_float(q0.w);
        float v2 = __int_as_float(q1.y), v3 = __int_as_float(q1.w);
        float v4 = __int_as_float(q2.y), v5 = __int_as_float(q2.w);
        float v6 = __int_as_float(q3.y), v7 = __int_as_float(q3.w);
        acc.x = fmaf(v0, x0.x, acc.x); acc.y = fmaf(v0, x0.y, acc.y);
        acc.z = fmaf(v0, x0.z, acc.z); acc.w = fmaf(v0, x0.w, acc.w);
        acc.x = fmaf(v1, x1.x, acc.x); acc.y = fmaf(v1, x1.y, acc.y);
        acc.z = fmaf(v1, x1.z, acc.z); acc.w = fmaf(v1, x1.w, acc.w);
        acc.x = fmaf(v2, x2.x, acc.x); acc.y = fmaf(v2, x2.y, acc.y);
        acc.z = fmaf(v2, x2.z, acc.z); acc.w = fmaf(v2, x2.w, acc.w);
        acc.x = fmaf(v3, x3.x, acc.x); acc.y = fmaf(v3, x3.y, acc.y);
        acc.z = fmaf(v3, x3.z, acc.z); acc.w = fmaf(v3, x3.w, acc.w);
        acc.x = fmaf(v4, x4.x, acc.x); acc.y = fmaf(v4, x4.y, acc.y);
        acc.z = fmaf(v4, x4.z, acc.z); acc.w = fmaf(v4, x4.w, acc.w);
        acc.x = fmaf(v5, x5.x, acc.x); acc.y = fmaf(v5, x5.y, acc.y);
        acc.z = fmaf(v5, x5.z, acc.z); acc.w = fmaf(v5, x5.w, acc.w);
        acc.x = fmaf(v6, x6.x, acc.x); acc.y = fmaf(v6, x6.y, acc.y);
        acc.z = fmaf(v6, x6.z, acc.z); acc.w = fmaf(v6, x6.w, acc.w);
        acc.x = fmaf(v7, x7.x, acc.x); acc.y = fmaf(v7, x7.y, acc.y);
        acc.z = fmaf(v7, x7.z, acc.z); acc.w = fmaf(v7, x7.w, acc.w);
        b += 8;
    } while (b < c);

    size_t base = (size_t)row * D;
    float4 ev = ldg_f4_pol((const float4*)(ego + base) + hl, pF);
    float dot = acc.x * ev.x + acc.y * ev.y + acc.z * ev.z + acc.w * ev.w;
    float ssy = acc.x * acc.x + acc.y * acc.y + acc.z * acc.z + acc.w * acc.w;
    float sse = ev.x * ev.x + ev.y * ev.y + ev.z * ev.z + ev.w * ev.w;
    #pragma unroll
    for (int o = 8; o; o >>= 1) {
        dot += __shfl_xor_sync(0xffffffffu, dot, o);
        ssy += __shfl_xor_sync(0xffffffffu, ssy, o);
        sse += __shfl_xor_sync(0xffffffffu, sse, o);
    }
    float w = dot / (fmaxf(sqrtf(ssy), EPS) * fmaxf(sqrtf(sse), EPS));
    acc.x *= w; acc.y *= w; acc.z *= w; acc.w *= w;

    if (FINAL) {
        float4 a = ldg_f4_pol((const float4*)(y0 + base) + hl, pF);
        float4 bb = ldg_f4_pol((const float4*)(y1 + base) + hl, pF);
        float4 cc = ldg_f4_pol((const float4*)(y2 + base) + hl, pF);
        acc.x += ev.x + a.x + bb.x + cc.x;
        acc.y += ev.y + a.y + bb.y + cc.y;
        acc.z += ev.z + a.z + bb.z + cc.z;
        acc.w += ev.w + a.w + bb.w + cc.w;
        ((float4*)(y + base))[hl] = acc;   // final output: default policy
        if (hl == 0) cnt[row] = 0;         // restore zero invariant for next call
    } else {
        stg_f4_pol((float4*)(y + base) + hl, acc, pL);
    }
}

extern "C" void kernel_launch(void* const* d_in, const int* in_sizes, int n_in,
                              void* d_out, int out_size) {
    const int*   adj_row  = (const int*)d_in[0];
    const int*   adj_col  = (const int*)d_in[1];
    const float* adj_val  = (const float*)d_in[2];
    const float* user_fea = (const float*)d_in[3];
    const float* item_fea = (const float*)d_in[4];
    const float* g_emb_u  = (const float*)d_in[5];
    const float* g_emb_i  = (const float*)d_in[6];
    const float* mlp_w    = (const float*)d_in[7];
    const float* mlp_b    = (const float*)d_in[8];
    float* acc = (float*)d_out;

    float *ego_p, *b0, *b1, *b2;
    int *cnt_p; int2 *elle_p;
    cudaGetSymbolAddress((void**)&ego_p,  g_ego);
    cudaGetSymbolAddress((void**)&b0,     g_buf0);
    cudaGetSymbolAddress((void**)&b1,     g_buf1);
    cudaGetSymbolAddress((void**)&b2,     g_buf2);
    cudaGetSymbolAddress((void**)&cnt_p,  g_cnt);
    cudaGetSymbolAddress((void**)&elle_p, g_elle);

    // cnt is zero on entry (zero-init on load; FINAL layer restores it each call)
    k_preamble<<<PRE_BLOCKS, 256>>>(item_fea, mlp_w, mlp_b, g_emb_i,
                                    adj_row, adj_col, adj_val,
                                    user_fea, g_emb_u,
                                    cnt_p, elle_p, ego_p);

    int lgrid = (N_NUM / 2 + 7) / 8;
    k_layer_t<false><<<lgrid, 256>>>(ego_p, b0, cnt_p, elle_p, ego_p, b0, b1, b2);
    k_layer_t<false><<<lgrid, 256>>>(b0,    b1, cnt_p, elle_p, ego_p, b0, b1, b2);
    k_layer_t<false><<<lgrid, 256>>>(b1,    b2, cnt_p, elle_p, ego_p, b0, b1, b2);
    k_layer_t<true><<<lgrid, 256>>>(b2,    acc, cnt_p, elle_p, ego_p, b0, b1, b2);
}